// round 14
// baseline (speedup 1.0000x reference)
#include <cuda_runtime.h>
#include <cuda_fp16.h>
#include <cstdint>
#include <cstddef>

#define BATCH 8
#define NPTS 16384
#define FDIM 6
#define MCENT 128
#define KNN_K 16
#define DOUT 768
#define NSLOT (BATCH * MCENT * KNN_K)   // 16384 gathered slots
#define FPS_SHARDS 2
#define SHARD_PTS (NPTS / FPS_SHARDS)   // 8192

// ---------------- scratch ----------------
__device__ __align__(16) float4 g_pts[BATCH * NPTS];
__device__ int    g_fidx[BATCH * MCENT];
__device__ float4 g_cent[BATCH * MCENT];
__device__ int    g_knn[BATCH * MCENT * KNN_K];
__device__ __align__(16) __half g_h1[(size_t)NSLOT * 256];
__device__ __align__(16) __half g_h2[(size_t)NSLOT * 512];
__device__ __align__(16) __half g_h3[(size_t)NSLOT * 768];
__device__ __align__(16) __half g_pooled[BATCH * MCENT * DOUT];
__device__ __align__(16) __half g_t1[BATCH * MCENT * DOUT];
__device__ __align__(16) float  g_tok[BATCH * MCENT * DOUT];
// FPS per-iteration exchange slots (keys zeroed each call by pack_pts_kernel)
__device__ unsigned long long g_sh[BATCH * MCENT * FPS_SHARDS];
__device__ __align__(16) float4 g_shc[BATCH * MCENT * FPS_SHARDS];
// half weights, k-pair interleaved: [K/2][N] half2
__device__ __align__(16) __half2 g_w1i[128 * 512];
__device__ __align__(16) __half2 g_w2i[256 * 768];
__device__ __align__(16) __half2 g_w3i[384 * 768];
__device__ __align__(16) __half2 g_wn0i[384 * 768];
__device__ __align__(16) __half2 g_wn1i[384 * 768];

// ---------------- pack coordinates -> float4 points; reset FPS key slots ----------------
__global__ void pack_pts_kernel(const float* __restrict__ coords) {
    int i = blockIdx.x * blockDim.x + threadIdx.x;
    if (i < BATCH * NPTS) {
        const float* p = coords + (size_t)i * 5;
        g_pts[i] = make_float4(p[1], p[2], p[3], p[4]);
    }
    if (i < BATCH * MCENT * FPS_SHARDS) g_sh[i] = 0ull;
}

// ---------------- interleave weights: [K,N] fp32 -> [K/2][N] half2 ----------------
__global__ void interleave_w_kernel(const float* __restrict__ W, __half2* __restrict__ dst,
                                    int K, int N) {
    int i = blockIdx.x * blockDim.x + threadIdx.x;
    int total = (K / 2) * N;
    if (i < total) {
        int k2 = i / N, n = i - k2 * N;
        dst[i] = __floats2half2_rn(W[(size_t)(2 * k2) * N + n], W[(size_t)(2 * k2 + 1) * N + n]);
    }
}

__device__ __forceinline__ float4 ld_volatile_f4(const float4* p) {
    float4 v;
    asm volatile("ld.volatile.global.v4.f32 {%0,%1,%2,%3}, [%4];"
                 : "=f"(v.x), "=f"(v.y), "=f"(v.z), "=f"(v.w) : "l"(p) : "memory");
    return v;
}
__device__ __forceinline__ void st_volatile_f4(float4* p, float4 v) {
    asm volatile("st.volatile.global.v4.f32 [%0], {%1,%2,%3,%4};"
                 :: "l"(p), "f"(v.x), "f"(v.y), "f"(v.z), "f"(v.w) : "memory");
}

// ---------------- 2-shard FPS: slot-per-iteration exchange (key + coords) ----------------
// grid = BATCH * FPS_SHARDS = 16 blocks of 1024 threads; 160KB smem -> 1 CTA/SM, co-resident.
__global__ void __launch_bounds__(1024) fps2_kernel() {
    extern __shared__ char sm[];
    float4* spts = (float4*)sm;                          // SHARD_PTS float4 (128KB)
    float*  mind = (float*)(sm + SHARD_PTS * 16);        // SHARD_PTS floats (32KB)
    __shared__ float  redv[32];
    __shared__ int    redi[32];
    __shared__ float4 sq;

    const int blk = blockIdx.x;
    const int b = blk >> 1, shard = blk & 1;
    const int base = shard * SHARD_PTS;
    const int tid = threadIdx.x, lane = tid & 31, warp = tid >> 5;
    const float4* P = g_pts + (size_t)b * NPTS;

    // load shard into smem
#pragma unroll
    for (int j = 0; j < SHARD_PTS / 1024; j++) {
        int i = tid + j * 1024;
        spts[i] = P[base + i];
    }
    if (tid == 0) {
        if (shard == 0) {
            g_fidx[b * MCENT] = 0;
            g_cent[b * MCENT] = P[0];
        }
        sq = P[0];
    }
    __syncthreads();

    for (int it = 1; it < MCENT; it++) {
        const float4 q = sq;
        float bestv = -1.0f;
        int   besti = 0x7fffffff;
#pragma unroll
        for (int j = 0; j < SHARD_PTS / 1024; j++) {
            const int i = tid + j * 1024;
            float4 p = spts[i];
            float dx = p.x - q.x, dy = p.y - q.y, dz = p.z - q.z, dw = p.w - q.w;
            float d = dx * dx + dy * dy + dz * dz + dw * dw;
            float md = (it == 1) ? d : fminf(mind[i], d);
            mind[i] = md;
            const int gi = base + i;
            if (md > bestv || (md == bestv && gi < besti)) { bestv = md; besti = gi; }
        }
#pragma unroll
        for (int off = 16; off > 0; off >>= 1) {
            float ov = __shfl_down_sync(0xffffffffu, bestv, off);
            int   oi = __shfl_down_sync(0xffffffffu, besti, off);
            if (ov > bestv || (ov == bestv && oi < besti)) { bestv = ov; besti = oi; }
        }
        if (lane == 0) { redv[warp] = bestv; redi[warp] = besti; }
        __syncthreads();
        if (warp == 0) {
            // stage-2 warp-parallel reduce over 32 partials
            float v = redv[lane];
            int   idx = redi[lane];
#pragma unroll
            for (int off = 16; off > 0; off >>= 1) {
                float ov = __shfl_down_sync(0xffffffffu, v, off);
                int   oi = __shfl_down_sync(0xffffffffu, idx, off);
                if (ov > v || (ov == v && oi < idx)) { v = ov; idx = oi; }
            }
            if (lane == 0) {
                // pack: distances >= 0 so float bits monotonic; ~idx => ties pick min idx.
                // low 32 bits always >= 0xFFFFC000, so 0 is a safe "empty" sentinel.
                unsigned long long mine =
                    ((unsigned long long)__float_as_uint(v) << 32) |
                    (unsigned long long)(0xFFFFFFFFu - (unsigned)idx);
                float4 mc = spts[idx - base];
                const int slot = (b * MCENT + it) * FPS_SHARDS;
                st_volatile_f4(&g_shc[slot + shard], mc);   // coords first
                __threadfence();                            // release
                *((volatile unsigned long long*)&g_sh[slot + shard]) = mine;
                unsigned long long peer;
                do {
                    peer = *((volatile unsigned long long*)&g_sh[slot + (shard ^ 1)]);
                } while (peer == 0ull);
                __threadfence();                            // acquire
                float4 wc;
                int widx;
                if (mine > peer) {
                    wc = mc;
                    widx = idx;
                } else {
                    wc = ld_volatile_f4(&g_shc[slot + (shard ^ 1)]);
                    widx = (int)(0xFFFFFFFFu - (unsigned)(peer & 0xFFFFFFFFull));
                }
                if (shard == 0) {
                    g_fidx[b * MCENT + it] = widx;
                    g_cent[b * MCENT + it] = wc;
                }
                sq = wc;
            }
        }
        __syncthreads();
    }
}

// ---------------- kNN ----------------
__device__ __forceinline__ bool dless(float d1, int i1, float d2, int i2) {
    return (d1 < d2) || (d1 == d2 && i1 < i2);
}

__global__ void __launch_bounds__(256) knn_kernel() {
    const int bm = blockIdx.x;
    const int b = bm / MCENT;
    const int tid = threadIdx.x;
    float4 c = g_cent[bm];
    const float4* P = g_pts + (size_t)b * NPTS;

    float ld[KNN_K];
    int   li[KNN_K];
#pragma unroll
    for (int s = 0; s < KNN_K; s++) { ld[s] = 3.0e38f; li[s] = 0x7fffffff; }

    for (int i = tid; i < NPTS; i += 256) {
        float4 p = P[i];
        float dx = p.x - c.x, dy = p.y - c.y, dz = p.z - c.z, dw = p.w - c.w;
        float d = dx * dx + dy * dy + dz * dz + dw * dw;
        if (dless(d, i, ld[KNN_K - 1], li[KNN_K - 1])) {
            ld[KNN_K - 1] = d; li[KNN_K - 1] = i;
#pragma unroll
            for (int s = KNN_K - 1; s > 0; s--) {
                if (dless(ld[s], li[s], ld[s - 1], li[s - 1])) {
                    float td = ld[s]; ld[s] = ld[s - 1]; ld[s - 1] = td;
                    int   ti = li[s]; li[s] = li[s - 1]; li[s - 1] = ti;
                }
            }
        }
    }

    __shared__ float sd[256][KNN_K];
    __shared__ int   si[256][KNN_K];
    __shared__ float wv[8];
    __shared__ int   wi[8];
    __shared__ int   fi;
#pragma unroll
    for (int s = 0; s < KNN_K; s++) { sd[tid][s] = ld[s]; si[tid][s] = li[s]; }
    __syncthreads();

    int pos = 0;
    for (int r = 0; r < KNN_K; r++) {
        float hv = sd[tid][pos];
        int   hi = si[tid][pos];
        float v = hv; int idx = hi;
#pragma unroll
        for (int off = 16; off > 0; off >>= 1) {
            float ov = __shfl_down_sync(0xffffffffu, v, off);
            int   oi = __shfl_down_sync(0xffffffffu, idx, off);
            if (dless(ov, oi, v, idx)) { v = ov; idx = oi; }
        }
        if ((tid & 31) == 0) { wv[tid >> 5] = v; wi[tid >> 5] = idx; }
        __syncthreads();
        if (tid == 0) {
            float bv = wv[0]; int bi = wi[0];
#pragma unroll
            for (int w = 1; w < 8; w++)
                if (dless(wv[w], wi[w], bv, bi)) { bv = wv[w]; bi = wi[w]; }
            fi = bi;
            g_knn[bm * KNN_K + r] = bi;
        }
        __syncthreads();
        if (hi == fi) pos++;
        __syncthreads();
    }
}

// ---------------- layer 0 on GATHERED slots ----------------
__global__ void __launch_bounds__(256) mlp0g_kernel(const float* __restrict__ f,
                                                    const float* __restrict__ W0,
                                                    const float* __restrict__ b0) {
    __shared__ float w[FDIM * 256];
    __shared__ float sb[256];
    __shared__ int   sidx[32];
    int tid = threadIdx.x;
#pragma unroll
    for (int i = 0; i < FDIM; i++) w[i * 256 + tid] = W0[i * 256 + tid];
    sb[tid] = b0[tid];
    int p0 = blockIdx.x * 32;
    if (tid < 32) {
        int p = p0 + tid;
        int bm = p >> 4;
        int b = bm >> 7;
        sidx[tid] = b * NPTS + g_knn[p];
    }
    __syncthreads();
    for (int pp = 0; pp < 32; pp++) {
        const float* fp = f + (size_t)sidx[pp] * FDIM;
        float acc = sb[tid];
#pragma unroll
        for (int k = 0; k < FDIM; k++) acc += fp[k] * w[k * 256 + tid];
        g_h1[(size_t)(p0 + pp) * 256 + tid] = __float2half_rn(fmaxf(acc, 0.0f));
    }
}

// ---------------- FP16 tensor-core GEMM ----------------
#define GF_RELU 1
#define GF_F32OUT 2
#define GF_POOL 4     // fused 16-row maxpool epilogue -> half output [M/16, N]

__device__ __forceinline__ void mma_f16(float* c, const uint32_t* a, const uint32_t* b) {
    asm volatile(
        "mma.sync.aligned.m16n8k16.row.col.f32.f16.f16.f32 "
        "{%0,%1,%2,%3}, {%4,%5,%6,%7}, {%8,%9}, {%0,%1,%2,%3};\n"
        : "+f"(c[0]), "+f"(c[1]), "+f"(c[2]), "+f"(c[3])
        : "r"(a[0]), "r"(a[1]), "r"(a[2]), "r"(a[3]), "r"(b[0]), "r"(b[1]));
}

__device__ __forceinline__ void cp16(void* dst, const void* src) {
    uint32_t d = (uint32_t)__cvta_generic_to_shared(dst);
    asm volatile("cp.async.cg.shared.global [%0], [%1], 16;\n" :: "r"(d), "l"(src));
}
__device__ __forceinline__ void cp_commit() { asm volatile("cp.async.commit_group;\n"); }
template <int N>
__device__ __forceinline__ void cp_wait() { asm volatile("cp.async.wait_group %0;\n" :: "n"(N)); }

#define AS2_STRIDE 20
#define BS2_STRIDE 136
#define AS2_SZ (128 * AS2_STRIDE)
#define BS2_SZ (16 * BS2_STRIDE)
#define GEMM_SMEM ((2 * AS2_SZ + 2 * BS2_SZ) * 4)   // 37888 bytes

__global__ void __launch_bounds__(128, 2) f16gemm_kernel(
    const __half* __restrict__ A, const __half2* __restrict__ B2,
    const float* __restrict__ bias, void* __restrict__ Cout,
    int Mdim, int Ndim, int Kdim, int flags)
{
    extern __shared__ uint32_t S[];
    uint32_t* As = S;
    uint32_t* Bs = S + 2 * AS2_SZ;

    const int tid = threadIdx.x;
    const int wid = tid >> 5, lane = tid & 31;
    const int grp = lane >> 2, tig = lane & 3;
    const int warp_m = (wid >> 1) * 64;
    const int warp_n = (wid & 1) * 64;
    const int rowBase = blockIdx.y * 128;
    const int colBase = blockIdx.x * 128;

    float acc[4][8][4];
#pragma unroll
    for (int i = 0; i < 4; i++)
#pragma unroll
        for (int j = 0; j < 8; j++)
#pragma unroll
            for (int t = 0; t < 4; t++) acc[i][j][t] = 0.0f;

    const int nk = Kdim >> 5;

#define LOAD_STAGE(kt)                                                             \
    {                                                                              \
        const int _s = (kt) & 1;                                                   \
        uint32_t* _as = As + _s * AS2_SZ;                                          \
        uint32_t* _bs = Bs + _s * BS2_SZ;                                          \
        _Pragma("unroll")                                                          \
        for (int _i = 0; _i < 4; _i++) {                                           \
            int _idx = _i * 128 + tid;                                             \
            int _r = _idx >> 2, _c4 = (_idx & 3) << 2;                             \
            cp16(_as + _r * AS2_STRIDE + _c4,                                      \
                 A + (size_t)(rowBase + _r) * Kdim + (kt) * 32 + _c4 * 2);         \
        }                                                                          \
        _Pragma("unroll")                                                          \
        for (int _i = 0; _i < 4; _i++) {                                           \
            int _idx = _i * 128 + tid;                                             \
            int _r = _idx >> 5, _c4 = (_idx & 31) << 2;                            \
            cp16(_bs + _r * BS2_STRIDE + _c4,                                      \
                 B2 + (size_t)((kt) * 16 + _r) * Ndim + colBase + _c4);            \
        }                                                                          \
    }

    LOAD_STAGE(0); cp_commit();
    LOAD_STAGE(1); cp_commit();

    for (int kt = 0; kt < nk; kt++) {
        cp_wait<1>();
        __syncthreads();
        const int s = kt & 1;
        const uint32_t* as = As + s * AS2_SZ;
        const uint32_t* bs = Bs + s * BS2_SZ;
#pragma unroll
        for (int k16 = 0; k16 < 2; k16++) {
            const int k2b = k16 * 8;
            uint32_t af[4][4];
            uint32_t bf[8][2];
#pragma unroll
            for (int mt = 0; mt < 4; mt++) {
                const uint32_t* ap = as + (size_t)(warp_m + mt * 16 + grp) * AS2_STRIDE + k2b;
                af[mt][0] = ap[tig];
                af[mt][1] = ap[8 * AS2_STRIDE + tig];
                af[mt][2] = ap[tig + 4];
                af[mt][3] = ap[8 * AS2_STRIDE + tig + 4];
            }
#pragma unroll
            for (int nt = 0; nt < 8; nt++) {
                const int col = warp_n + nt * 8 + grp;
                bf[nt][0] = bs[(size_t)(k2b + tig) * BS2_STRIDE + col];
                bf[nt][1] = bs[(size_t)(k2b + tig + 4) * BS2_STRIDE + col];
            }
#pragma unroll
            for (int mt = 0; mt < 4; mt++)
#pragma unroll
                for (int nt = 0; nt < 8; nt++)
                    mma_f16(acc[mt][nt], af[mt], bf[nt]);
        }
        __syncthreads();
        if (kt + 2 < nk) LOAD_STAGE(kt + 2);
        cp_commit();
    }

    const int relu = flags & GF_RELU;
    const int f32o = flags & GF_F32OUT;
    const int pool = flags & GF_POOL;
#pragma unroll
    for (int nt = 0; nt < 8; nt++) {
        const int cc = colBase + warp_n + nt * 8 + 2 * tig;
        const float bv0 = bias[cc];
        const float bv1 = bias[cc + 1];
#pragma unroll
        for (int mt = 0; mt < 4; mt++) {
            float v0 = acc[mt][nt][0] + bv0;
            float v1 = acc[mt][nt][1] + bv1;
            float v2 = acc[mt][nt][2] + bv0;
            float v3 = acc[mt][nt][3] + bv1;
            if (relu) {
                v0 = fmaxf(v0, 0.f); v1 = fmaxf(v1, 0.f);
                v2 = fmaxf(v2, 0.f); v3 = fmaxf(v3, 0.f);
            }
            if (pool) {
                // rows warp_m+mt*16+{grp, grp+8} -> pool group pr; reduce over grp lanes
                float c0 = fmaxf(v0, v2);
                float c1 = fmaxf(v1, v3);
#pragma unroll
                for (int off = 4; off <= 16; off <<= 1) {
                    c0 = fmaxf(c0, __shfl_xor_sync(0xffffffffu, c0, off));
                    c1 = fmaxf(c1, __shfl_xor_sync(0xffffffffu, c1, off));
                }
                if (grp == 0) {
                    const int pr = (rowBase + warp_m + mt * 16) >> 4;
                    __half2* C = (__half2*)Cout;
                    C[((size_t)pr * Ndim + cc) >> 1] = __floats2half2_rn(c0, c1);
                }
            } else {
                const int r0 = rowBase + warp_m + mt * 16 + grp;
                if (f32o) {
                    float* C = (float*)Cout;
                    *(float2*)(C + (size_t)r0 * Ndim + cc) = make_float2(v0, v1);
                    *(float2*)(C + (size_t)(r0 + 8) * Ndim + cc) = make_float2(v2, v3);
                } else {
                    __half2* C = (__half2*)Cout;
                    C[((size_t)r0 * Ndim + cc) >> 1] = __floats2half2_rn(v0, v1);
                    C[((size_t)(r0 + 8) * Ndim + cc) >> 1] = __floats2half2_rn(v2, v3);
                }
            }
        }
    }
}

// ---------------- fused rank + scatter + mask ----------------
__global__ void __launch_bounds__(256) scatter_fused_kernel(float* __restrict__ out, long out_size) {
    const int bm = blockIdx.x;
    const int b = bm >> 7;
    const int m = bm & 127;
    const int tid = threadIdx.x;
    __shared__ float ts[MCENT];
    __shared__ int cnt;
    if (tid < MCENT) ts[tid] = g_cent[b * MCENT + tid].w;
    if (tid == 0) cnt = 0;
    __syncthreads();
    const float t = ts[m];
    if (tid < MCENT) {
        bool pred = (ts[tid] < t) || (ts[tid] == t && tid < m);
        unsigned ball = __ballot_sync(0xffffffffu, pred);
        if ((tid & 31) == 0) atomicAdd(&cnt, __popc(ball));
    }
    __syncthreads();
    const int r = cnt;
    const size_t dst = ((size_t)b * MCENT + r) * DOUT;
    const float* src = g_tok + (size_t)bm * DOUT;
    for (int d = tid; d < DOUT; d += 256)
        if ((long)(dst + d) < out_size) out[dst + d] = src[d];
    if (tid == 0) {
        float4 c = g_cent[bm];
        size_t cb = (size_t)BATCH * MCENT * DOUT + ((size_t)b * MCENT + r) * 4;
        if ((long)(cb + 3) < out_size) {
            out[cb + 0] = c.x; out[cb + 1] = c.y; out[cb + 2] = c.z; out[cb + 3] = c.w;
        }
        size_t mb = (size_t)BATCH * MCENT * DOUT + (size_t)BATCH * MCENT * 4
                    + (size_t)b * MCENT + r;
        if ((long)mb < out_size) out[mb] = 1.0f;
    }
}

// ---------------- launch ----------------
extern "C" void kernel_launch(void* const* d_in, const int* in_sizes, int n_in,
                              void* d_out, int out_size) {
    const float* coords = (const float*)d_in[0];
    const float* feats  = (const float*)d_in[1];
    const float* W0 = (const float*)d_in[2];  const float* b0 = (const float*)d_in[3];
    const float* W1 = (const float*)d_in[4];  const float* b1 = (const float*)d_in[5];
    const float* W2 = (const float*)d_in[6];  const float* b2 = (const float*)d_in[7];
    const float* W3 = (const float*)d_in[8];  const float* b3 = (const float*)d_in[9];
    const float* Wn0 = (const float*)d_in[10]; const float* bn0 = (const float*)d_in[11];
    const float* Wn1 = (const float*)d_in[12]; const float* bn1 = (const float*)d_in[13];
    float* out = (float*)d_out;

    __half *h1, *h2, *h3, *pooled, *t1;
    float *tok;
    __half2 *w1i, *w2i, *w3i, *wn0i, *wn1i;
    cudaGetSymbolAddress((void**)&h1, g_h1);
    cudaGetSymbolAddress((void**)&h2, g_h2);
    cudaGetSymbolAddress((void**)&h3, g_h3);
    cudaGetSymbolAddress((void**)&pooled, g_pooled);
    cudaGetSymbolAddress((void**)&t1, g_t1);
    cudaGetSymbolAddress((void**)&tok, g_tok);
    cudaGetSymbolAddress((void**)&w1i, g_w1i);
    cudaGetSymbolAddress((void**)&w2i, g_w2i);
    cudaGetSymbolAddress((void**)&w3i, g_w3i);
    cudaGetSymbolAddress((void**)&wn0i, g_wn0i);
    cudaGetSymbolAddress((void**)&wn1i, g_wn1i);

    const int FPS_SMEM = SHARD_PTS * 16 + SHARD_PTS * 4;   // 163840 bytes
    cudaFuncSetAttribute(fps2_kernel, cudaFuncAttributeMaxDynamicSharedMemorySize, FPS_SMEM);

    const int BN = BATCH * NPTS;        // 131072
    const int BM = BATCH * MCENT;       // 1024

    // fork side stream for weight interleave (hidden under geometry chain)
    static cudaStream_t sideS = nullptr;
    static cudaEvent_t evF = nullptr, evJ = nullptr;
    if (sideS == nullptr) {
        if (cudaStreamCreateWithFlags(&sideS, cudaStreamNonBlocking) != cudaSuccess) sideS = nullptr;
        if (cudaEventCreateWithFlags(&evF, cudaEventDisableTiming) != cudaSuccess) evF = nullptr;
        if (cudaEventCreateWithFlags(&evJ, cudaEventDisableTiming) != cudaSuccess) evJ = nullptr;
    }
    const bool fork = (sideS != nullptr) && (evF != nullptr) && (evJ != nullptr);
    cudaStream_t ws = fork ? sideS : (cudaStream_t)0;

    if (fork) {
        cudaEventRecord(evF, 0);
        cudaStreamWaitEvent(ws, evF, 0);
    }
    interleave_w_kernel<<<(128 * 512 + 255) / 256, 256, 0, ws>>>(W1, w1i, 256, 512);
    interleave_w_kernel<<<(256 * 768 + 255) / 256, 256, 0, ws>>>(W2, w2i, 512, 768);
    interleave_w_kernel<<<(384 * 768 + 255) / 256, 256, 0, ws>>>(W3, w3i, 768, 768);
    interleave_w_kernel<<<(384 * 768 + 255) / 256, 256, 0, ws>>>(Wn0, wn0i, 768, 768);
    interleave_w_kernel<<<(384 * 768 + 255) / 256, 256, 0, ws>>>(Wn1, wn1i, 768, 768);
    if (fork) cudaEventRecord(evJ, ws);

    // geometry chain (critical path)
    pack_pts_kernel<<<(BN + 255) / 256, 256>>>(coords);
    fps2_kernel<<<BATCH * FPS_SHARDS, 1024, FPS_SMEM>>>();
    knn_kernel<<<BM, 256>>>();

    // gathered per-slot MLP (16384 rows)
    mlp0g_kernel<<<NSLOT / 32, 256>>>(feats, W0, b0);

    if (fork) cudaStreamWaitEvent(0, evJ, 0);

    {
        dim3 g(512 / 128, NSLOT / 128);
        f16gemm_kernel<<<g, 128, GEMM_SMEM>>>(h1, w1i, b1, h2, NSLOT, 512, 256, GF_RELU);
    }
    {
        dim3 g(768 / 128, NSLOT / 128);
        f16gemm_kernel<<<g, 128, GEMM_SMEM>>>(h2, w2i, b2, h3, NSLOT, 768, 512, GF_RELU);
    }
    {
        // GEMM3 with fused 16-row maxpool: writes pooled [1024, 768] directly
        dim3 g(768 / 128, NSLOT / 128);
        f16gemm_kernel<<<g, 128, GEMM_SMEM>>>(h3, w3i, b3, pooled, NSLOT, 768, 768, GF_POOL);
    }

    {
        dim3 g(768 / 128, BM / 128);
        f16gemm_kernel<<<g, 128, GEMM_SMEM>>>(pooled, wn0i, bn0, t1, BM, 768, 768, GF_RELU);
        f16gemm_kernel<<<g, 128, GEMM_SMEM>>>(t1, wn1i, bn1, tok, BM, 768, 768, GF_F32OUT);
    }

    scatter_fused_kernel<<<BM, 256>>>(out, (long)out_size);
}

// round 15
// speedup vs baseline: 1.1150x; 1.1150x over previous
#include <cuda_runtime.h>
#include <cuda_fp16.h>
#include <cstdint>
#include <cstddef>

#define BATCH 8
#define NPTS 16384
#define FDIM 6
#define MCENT 128
#define KNN_K 16
#define DOUT 768
#define NSLOT (BATCH * MCENT * KNN_K)   // 16384 gathered slots
#define FPS_SHARDS 2
#define SHARD_PTS (NPTS / FPS_SHARDS)   // 8192

// ---------------- scratch ----------------
__device__ __align__(16) float4 g_pts[BATCH * NPTS];
__device__ int    g_fidx[BATCH * MCENT];
__device__ float4 g_cent[BATCH * MCENT];
__device__ int    g_knn[BATCH * MCENT * KNN_K];
__device__ __align__(16) __half g_h1[(size_t)NSLOT * 256];
__device__ __align__(16) __half g_h2[(size_t)NSLOT * 512];
__device__ __align__(16) __half g_h3[(size_t)NSLOT * 768];
__device__ __align__(16) __half g_pooled[BATCH * MCENT * DOUT];
__device__ __align__(16) __half g_t1[BATCH * MCENT * DOUT];
__device__ __align__(16) float  g_tok[BATCH * MCENT * DOUT];
// FPS per-iteration exchange slots (zeroed each call by pack_pts_kernel)
__device__ unsigned long long g_sh[BATCH * MCENT * FPS_SHARDS];
// half weights, k-pair interleaved: [K/2][N] half2
__device__ __align__(16) __half2 g_w1i[128 * 512];
__device__ __align__(16) __half2 g_w2i[256 * 768];
__device__ __align__(16) __half2 g_w3i[384 * 768];
__device__ __align__(16) __half2 g_wn0i[384 * 768];
__device__ __align__(16) __half2 g_wn1i[384 * 768];

// ---------------- pack coordinates -> float4 points; reset FPS slots ----------------
__global__ void pack_pts_kernel(const float* __restrict__ coords) {
    int i = blockIdx.x * blockDim.x + threadIdx.x;
    if (i < BATCH * NPTS) {
        const float* p = coords + (size_t)i * 5;
        g_pts[i] = make_float4(p[1], p[2], p[3], p[4]);
    }
    if (i < BATCH * MCENT * FPS_SHARDS) g_sh[i] = 0ull;
}

// ---------------- interleave weights: [K,N] fp32 -> [K/2][N] half2 ----------------
__global__ void interleave_w_kernel(const float* __restrict__ W, __half2* __restrict__ dst,
                                    int K, int N) {
    int i = blockIdx.x * blockDim.x + threadIdx.x;
    int total = (K / 2) * N;
    if (i < total) {
        int k2 = i / N, n = i - k2 * N;
        dst[i] = __floats2half2_rn(W[(size_t)(2 * k2) * N + n], W[(size_t)(2 * k2 + 1) * N + n]);
    }
}

// ---------------- 2-shard FPS: slot-per-iteration exchange (round-11 version) ----------------
// grid = BATCH * FPS_SHARDS = 16 blocks of 1024 threads; 160KB smem -> 1 CTA/SM, co-resident.
__global__ void __launch_bounds__(1024) fps2_kernel() {
    extern __shared__ char sm[];
    float4* spts = (float4*)sm;                          // SHARD_PTS float4 (128KB)
    float*  mind = (float*)(sm + SHARD_PTS * 16);        // SHARD_PTS floats (32KB)
    __shared__ float  redv[32];
    __shared__ int    redi[32];
    __shared__ float4 sq;

    const int blk = blockIdx.x;
    const int b = blk >> 1, shard = blk & 1;
    const int base = shard * SHARD_PTS;
    const int tid = threadIdx.x, lane = tid & 31, warp = tid >> 5;
    const float4* P = g_pts + (size_t)b * NPTS;

    // load shard into smem
#pragma unroll
    for (int j = 0; j < SHARD_PTS / 1024; j++) {
        int i = tid + j * 1024;
        spts[i] = P[base + i];
    }
    if (tid == 0) {
        if (shard == 0) {
            g_fidx[b * MCENT] = 0;
            g_cent[b * MCENT] = P[0];
        }
        sq = P[0];
    }
    __syncthreads();

    for (int it = 1; it < MCENT; it++) {
        const float4 q = sq;
        float bestv = -1.0f;
        int   besti = 0x7fffffff;
#pragma unroll
        for (int j = 0; j < SHARD_PTS / 1024; j++) {
            const int i = tid + j * 1024;
            float4 p = spts[i];
            float dx = p.x - q.x, dy = p.y - q.y, dz = p.z - q.z, dw = p.w - q.w;
            float d = dx * dx + dy * dy + dz * dz + dw * dw;
            float md = (it == 1) ? d : fminf(mind[i], d);
            mind[i] = md;
            const int gi = base + i;
            if (md > bestv || (md == bestv && gi < besti)) { bestv = md; besti = gi; }
        }
#pragma unroll
        for (int off = 16; off > 0; off >>= 1) {
            float ov = __shfl_down_sync(0xffffffffu, bestv, off);
            int   oi = __shfl_down_sync(0xffffffffu, besti, off);
            if (ov > bestv || (ov == bestv && oi < besti)) { bestv = ov; besti = oi; }
        }
        if (lane == 0) { redv[warp] = bestv; redi[warp] = besti; }
        __syncthreads();
        if (tid == 0) {
            float v = redv[0]; int idx = redi[0];
#pragma unroll
            for (int w = 1; w < 32; w++)
                if (redv[w] > v || (redv[w] == v && redi[w] < idx)) { v = redv[w]; idx = redi[w]; }
            // pack: distances >= 0 so float bits monotonic; ~idx => ties pick min idx.
            // low 32 bits always >= 0xFFFFC000, so 0 is a safe "empty" sentinel.
            unsigned long long mine =
                ((unsigned long long)__float_as_uint(v) << 32) |
                (unsigned long long)(0xFFFFFFFFu - (unsigned)idx);
            const int slotBase = (b * MCENT + it) * FPS_SHARDS;
            atomicExch(&g_sh[slotBase + shard], mine);           // globally visible publish
            unsigned long long peer;
            do {
                peer = *((volatile unsigned long long*)&g_sh[slotBase + (shard ^ 1)]);
            } while (peer == 0ull);
            unsigned long long best = (peer > mine) ? peer : mine;
            int widx = (int)(0xFFFFFFFFu - (unsigned)(best & 0xFFFFFFFFull));
            float4 nq = P[widx];
            if (shard == 0) {
                g_fidx[b * MCENT + it] = widx;
                g_cent[b * MCENT + it] = nq;
            }
            sq = nq;
        }
        __syncthreads();
    }
}

// ---------------- kNN ----------------
__device__ __forceinline__ bool dless(float d1, int i1, float d2, int i2) {
    return (d1 < d2) || (d1 == d2 && i1 < i2);
}

__global__ void __launch_bounds__(256) knn_kernel() {
    const int bm = blockIdx.x;
    const int b = bm / MCENT;
    const int tid = threadIdx.x;
    float4 c = g_cent[bm];
    const float4* P = g_pts + (size_t)b * NPTS;

    float ld[KNN_K];
    int   li[KNN_K];
#pragma unroll
    for (int s = 0; s < KNN_K; s++) { ld[s] = 3.0e38f; li[s] = 0x7fffffff; }

    for (int i = tid; i < NPTS; i += 256) {
        float4 p = P[i];
        float dx = p.x - c.x, dy = p.y - c.y, dz = p.z - c.z, dw = p.w - c.w;
        float d = dx * dx + dy * dy + dz * dz + dw * dw;
        if (dless(d, i, ld[KNN_K - 1], li[KNN_K - 1])) {
            ld[KNN_K - 1] = d; li[KNN_K - 1] = i;
#pragma unroll
            for (int s = KNN_K - 1; s > 0; s--) {
                if (dless(ld[s], li[s], ld[s - 1], li[s - 1])) {
                    float td = ld[s]; ld[s] = ld[s - 1]; ld[s - 1] = td;
                    int   ti = li[s]; li[s] = li[s - 1]; li[s - 1] = ti;
                }
            }
        }
    }

    __shared__ float sd[256][KNN_K];
    __shared__ int   si[256][KNN_K];
    __shared__ float wv[8];
    __shared__ int   wi[8];
    __shared__ int   fi;
#pragma unroll
    for (int s = 0; s < KNN_K; s++) { sd[tid][s] = ld[s]; si[tid][s] = li[s]; }
    __syncthreads();

    int pos = 0;
    for (int r = 0; r < KNN_K; r++) {
        float hv = sd[tid][pos];
        int   hi = si[tid][pos];
        float v = hv; int idx = hi;
#pragma unroll
        for (int off = 16; off > 0; off >>= 1) {
            float ov = __shfl_down_sync(0xffffffffu, v, off);
            int   oi = __shfl_down_sync(0xffffffffu, idx, off);
            if (dless(ov, oi, v, idx)) { v = ov; idx = oi; }
        }
        if ((tid & 31) == 0) { wv[tid >> 5] = v; wi[tid >> 5] = idx; }
        __syncthreads();
        if (tid == 0) {
            float bv = wv[0]; int bi = wi[0];
#pragma unroll
            for (int w = 1; w < 8; w++)
                if (dless(wv[w], wi[w], bv, bi)) { bv = wv[w]; bi = wi[w]; }
            fi = bi;
            g_knn[bm * KNN_K + r] = bi;
        }
        __syncthreads();
        if (hi == fi) pos++;
        __syncthreads();
    }
}

// ---------------- layer 0 on GATHERED slots ----------------
__global__ void __launch_bounds__(256) mlp0g_kernel(const float* __restrict__ f,
                                                    const float* __restrict__ W0,
                                                    const float* __restrict__ b0) {
    __shared__ float w[FDIM * 256];
    __shared__ float sb[256];
    __shared__ int   sidx[32];
    int tid = threadIdx.x;
#pragma unroll
    for (int i = 0; i < FDIM; i++) w[i * 256 + tid] = W0[i * 256 + tid];
    sb[tid] = b0[tid];
    int p0 = blockIdx.x * 32;
    if (tid < 32) {
        int p = p0 + tid;
        int bm = p >> 4;
        int b = bm >> 7;
        sidx[tid] = b * NPTS + g_knn[p];
    }
    __syncthreads();
    for (int pp = 0; pp < 32; pp++) {
        const float* fp = f + (size_t)sidx[pp] * FDIM;
        float acc = sb[tid];
#pragma unroll
        for (int k = 0; k < FDIM; k++) acc += fp[k] * w[k * 256 + tid];
        g_h1[(size_t)(p0 + pp) * 256 + tid] = __float2half_rn(fmaxf(acc, 0.0f));
    }
}

// ---------------- FP16 tensor-core GEMM ----------------
#define GF_RELU 1
#define GF_F32OUT 2
#define GF_POOL 4     // fused 16-row maxpool epilogue -> half output [M/16, N]

__device__ __forceinline__ void mma_f16(float* c, const uint32_t* a, const uint32_t* b) {
    asm volatile(
        "mma.sync.aligned.m16n8k16.row.col.f32.f16.f16.f32 "
        "{%0,%1,%2,%3}, {%4,%5,%6,%7}, {%8,%9}, {%0,%1,%2,%3};\n"
        : "+f"(c[0]), "+f"(c[1]), "+f"(c[2]), "+f"(c[3])
        : "r"(a[0]), "r"(a[1]), "r"(a[2]), "r"(a[3]), "r"(b[0]), "r"(b[1]));
}

__device__ __forceinline__ void cp16(void* dst, const void* src) {
    uint32_t d = (uint32_t)__cvta_generic_to_shared(dst);
    asm volatile("cp.async.cg.shared.global [%0], [%1], 16;\n" :: "r"(d), "l"(src));
}
__device__ __forceinline__ void cp_commit() { asm volatile("cp.async.commit_group;\n"); }
template <int N>
__device__ __forceinline__ void cp_wait() { asm volatile("cp.async.wait_group %0;\n" :: "n"(N)); }

#define AS2_STRIDE 20
#define BS2_STRIDE 136
#define AS2_SZ (128 * AS2_STRIDE)
#define BS2_SZ (16 * BS2_STRIDE)
#define GEMM_SMEM ((2 * AS2_SZ + 2 * BS2_SZ) * 4)   // 37888 bytes

__global__ void __launch_bounds__(128, 2) f16gemm_kernel(
    const __half* __restrict__ A, const __half2* __restrict__ B2,
    const float* __restrict__ bias, void* __restrict__ Cout,
    int Mdim, int Ndim, int Kdim, int flags)
{
    extern __shared__ uint32_t S[];
    uint32_t* As = S;
    uint32_t* Bs = S + 2 * AS2_SZ;

    const int tid = threadIdx.x;
    const int wid = tid >> 5, lane = tid & 31;
    const int grp = lane >> 2, tig = lane & 3;
    const int warp_m = (wid >> 1) * 64;
    const int warp_n = (wid & 1) * 64;
    const int rowBase = blockIdx.y * 128;
    const int colBase = blockIdx.x * 128;

    float acc[4][8][4];
#pragma unroll
    for (int i = 0; i < 4; i++)
#pragma unroll
        for (int j = 0; j < 8; j++)
#pragma unroll
            for (int t = 0; t < 4; t++) acc[i][j][t] = 0.0f;

    const int nk = Kdim >> 5;

#define LOAD_STAGE(kt)                                                             \
    {                                                                              \
        const int _s = (kt) & 1;                                                   \
        uint32_t* _as = As + _s * AS2_SZ;                                          \
        uint32_t* _bs = Bs + _s * BS2_SZ;                                          \
        _Pragma("unroll")                                                          \
        for (int _i = 0; _i < 4; _i++) {                                           \
            int _idx = _i * 128 + tid;                                             \
            int _r = _idx >> 2, _c4 = (_idx & 3) << 2;                             \
            cp16(_as + _r * AS2_STRIDE + _c4,                                      \
                 A + (size_t)(rowBase + _r) * Kdim + (kt) * 32 + _c4 * 2);         \
        }                                                                          \
        _Pragma("unroll")                                                          \
        for (int _i = 0; _i < 4; _i++) {                                           \
            int _idx = _i * 128 + tid;                                             \
            int _r = _idx >> 5, _c4 = (_idx & 31) << 2;                            \
            cp16(_bs + _r * BS2_STRIDE + _c4,                                      \
                 B2 + (size_t)((kt) * 16 + _r) * Ndim + colBase + _c4);            \
        }                                                                          \
    }

    LOAD_STAGE(0); cp_commit();
    LOAD_STAGE(1); cp_commit();

    for (int kt = 0; kt < nk; kt++) {
        cp_wait<1>();
        __syncthreads();
        const int s = kt & 1;
        const uint32_t* as = As + s * AS2_SZ;
        const uint32_t* bs = Bs + s * BS2_SZ;
#pragma unroll
        for (int k16 = 0; k16 < 2; k16++) {
            const int k2b = k16 * 8;
            uint32_t af[4][4];
            uint32_t bf[8][2];
#pragma unroll
            for (int mt = 0; mt < 4; mt++) {
                const uint32_t* ap = as + (size_t)(warp_m + mt * 16 + grp) * AS2_STRIDE + k2b;
                af[mt][0] = ap[tig];
                af[mt][1] = ap[8 * AS2_STRIDE + tig];
                af[mt][2] = ap[tig + 4];
                af[mt][3] = ap[8 * AS2_STRIDE + tig + 4];
            }
#pragma unroll
            for (int nt = 0; nt < 8; nt++) {
                const int col = warp_n + nt * 8 + grp;
                bf[nt][0] = bs[(size_t)(k2b + tig) * BS2_STRIDE + col];
                bf[nt][1] = bs[(size_t)(k2b + tig + 4) * BS2_STRIDE + col];
            }
#pragma unroll
            for (int mt = 0; mt < 4; mt++)
#pragma unroll
                for (int nt = 0; nt < 8; nt++)
                    mma_f16(acc[mt][nt], af[mt], bf[nt]);
        }
        __syncthreads();
        if (kt + 2 < nk) LOAD_STAGE(kt + 2);
        cp_commit();
    }

    const int relu = flags & GF_RELU;
    const int f32o = flags & GF_F32OUT;
    const int pool = flags & GF_POOL;
#pragma unroll
    for (int nt = 0; nt < 8; nt++) {
        const int cc = colBase + warp_n + nt * 8 + 2 * tig;
        const float bv0 = bias[cc];
        const float bv1 = bias[cc + 1];
#pragma unroll
        for (int mt = 0; mt < 4; mt++) {
            float v0 = acc[mt][nt][0] + bv0;
            float v1 = acc[mt][nt][1] + bv1;
            float v2 = acc[mt][nt][2] + bv0;
            float v3 = acc[mt][nt][3] + bv1;
            if (relu) {
                v0 = fmaxf(v0, 0.f); v1 = fmaxf(v1, 0.f);
                v2 = fmaxf(v2, 0.f); v3 = fmaxf(v3, 0.f);
            }
            if (pool) {
                // rows warp_m+mt*16+{grp, grp+8} -> one pool group; reduce over grp lanes
                float c0 = fmaxf(v0, v2);
                float c1 = fmaxf(v1, v3);
#pragma unroll
                for (int off = 4; off <= 16; off <<= 1) {
                    c0 = fmaxf(c0, __shfl_xor_sync(0xffffffffu, c0, off));
                    c1 = fmaxf(c1, __shfl_xor_sync(0xffffffffu, c1, off));
                }
                if (grp == 0) {
                    const int pr = (rowBase + warp_m + mt * 16) >> 4;
                    __half2* C = (__half2*)Cout;
                    C[((size_t)pr * Ndim + cc) >> 1] = __floats2half2_rn(c0, c1);
                }
            } else {
                const int r0 = rowBase + warp_m + mt * 16 + grp;
                if (f32o) {
                    float* C = (float*)Cout;
                    *(float2*)(C + (size_t)r0 * Ndim + cc) = make_float2(v0, v1);
                    *(float2*)(C + (size_t)(r0 + 8) * Ndim + cc) = make_float2(v2, v3);
                } else {
                    __half2* C = (__half2*)Cout;
                    C[((size_t)r0 * Ndim + cc) >> 1] = __floats2half2_rn(v0, v1);
                    C[((size_t)(r0 + 8) * Ndim + cc) >> 1] = __floats2half2_rn(v2, v3);
                }
            }
        }
    }
}

// ---------------- fused rank + scatter + mask ----------------
__global__ void __launch_bounds__(256) scatter_fused_kernel(float* __restrict__ out, long out_size) {
    const int bm = blockIdx.x;
    const int b = bm >> 7;
    const int m = bm & 127;
    const int tid = threadIdx.x;
    __shared__ float ts[MCENT];
    __shared__ int cnt;
    if (tid < MCENT) ts[tid] = g_cent[b * MCENT + tid].w;
    if (tid == 0) cnt = 0;
    __syncthreads();
    const float t = ts[m];
    if (tid < MCENT) {
        bool pred = (ts[tid] < t) || (ts[tid] == t && tid < m);
        unsigned ball = __ballot_sync(0xffffffffu, pred);
        if ((tid & 31) == 0) atomicAdd(&cnt, __popc(ball));
    }
    __syncthreads();
    const int r = cnt;
    const size_t dst = ((size_t)b * MCENT + r) * DOUT;
    const float* src = g_tok + (size_t)bm * DOUT;
    for (int d = tid; d < DOUT; d += 256)
        if ((long)(dst + d) < out_size) out[dst + d] = src[d];
    if (tid == 0) {
        float4 c = g_cent[bm];
        size_t cb = (size_t)BATCH * MCENT * DOUT + ((size_t)b * MCENT + r) * 4;
        if ((long)(cb + 3) < out_size) {
            out[cb + 0] = c.x; out[cb + 1] = c.y; out[cb + 2] = c.z; out[cb + 3] = c.w;
        }
        size_t mb = (size_t)BATCH * MCENT * DOUT + (size_t)BATCH * MCENT * 4
                    + (size_t)b * MCENT + r;
        if ((long)mb < out_size) out[mb] = 1.0f;
    }
}

// ---------------- launch ----------------
extern "C" void kernel_launch(void* const* d_in, const int* in_sizes, int n_in,
                              void* d_out, int out_size) {
    const float* coords = (const float*)d_in[0];
    const float* feats  = (const float*)d_in[1];
    const float* W0 = (const float*)d_in[2];  const float* b0 = (const float*)d_in[3];
    const float* W1 = (const float*)d_in[4];  const float* b1 = (const float*)d_in[5];
    const float* W2 = (const float*)d_in[6];  const float* b2 = (const float*)d_in[7];
    const float* W3 = (const float*)d_in[8];  const float* b3 = (const float*)d_in[9];
    const float* Wn0 = (const float*)d_in[10]; const float* bn0 = (const float*)d_in[11];
    const float* Wn1 = (const float*)d_in[12]; const float* bn1 = (const float*)d_in[13];
    float* out = (float*)d_out;

    __half *h1, *h2, *h3, *pooled, *t1;
    float *tok;
    __half2 *w1i, *w2i, *w3i, *wn0i, *wn1i;
    cudaGetSymbolAddress((void**)&h1, g_h1);
    cudaGetSymbolAddress((void**)&h2, g_h2);
    cudaGetSymbolAddress((void**)&h3, g_h3);
    cudaGetSymbolAddress((void**)&pooled, g_pooled);
    cudaGetSymbolAddress((void**)&t1, g_t1);
    cudaGetSymbolAddress((void**)&tok, g_tok);
    cudaGetSymbolAddress((void**)&w1i, g_w1i);
    cudaGetSymbolAddress((void**)&w2i, g_w2i);
    cudaGetSymbolAddress((void**)&w3i, g_w3i);
    cudaGetSymbolAddress((void**)&wn0i, g_wn0i);
    cudaGetSymbolAddress((void**)&wn1i, g_wn1i);

    const int FPS_SMEM = SHARD_PTS * 16 + SHARD_PTS * 4;   // 163840 bytes
    cudaFuncSetAttribute(fps2_kernel, cudaFuncAttributeMaxDynamicSharedMemorySize, FPS_SMEM);

    const int BN = BATCH * NPTS;        // 131072
    const int BM = BATCH * MCENT;       // 1024

    // fork side stream for weight interleave (hidden under geometry chain)
    static cudaStream_t sideS = nullptr;
    static cudaEvent_t evF = nullptr, evJ = nullptr;
    if (sideS == nullptr) {
        if (cudaStreamCreateWithFlags(&sideS, cudaStreamNonBlocking) != cudaSuccess) sideS = nullptr;
        if (cudaEventCreateWithFlags(&evF, cudaEventDisableTiming) != cudaSuccess) evF = nullptr;
        if (cudaEventCreateWithFlags(&evJ, cudaEventDisableTiming) != cudaSuccess) evJ = nullptr;
    }
    const bool fork = (sideS != nullptr) && (evF != nullptr) && (evJ != nullptr);
    cudaStream_t ws = fork ? sideS : (cudaStream_t)0;

    if (fork) {
        cudaEventRecord(evF, 0);
        cudaStreamWaitEvent(ws, evF, 0);
    }
    interleave_w_kernel<<<(128 * 512 + 255) / 256, 256, 0, ws>>>(W1, w1i, 256, 512);
    interleave_w_kernel<<<(256 * 768 + 255) / 256, 256, 0, ws>>>(W2, w2i, 512, 768);
    interleave_w_kernel<<<(384 * 768 + 255) / 256, 256, 0, ws>>>(W3, w3i, 768, 768);
    interleave_w_kernel<<<(384 * 768 + 255) / 256, 256, 0, ws>>>(Wn0, wn0i, 768, 768);
    interleave_w_kernel<<<(384 * 768 + 255) / 256, 256, 0, ws>>>(Wn1, wn1i, 768, 768);
    if (fork) cudaEventRecord(evJ, ws);

    // geometry chain (critical path)
    pack_pts_kernel<<<(BN + 255) / 256, 256>>>(coords);
    fps2_kernel<<<BATCH * FPS_SHARDS, 1024, FPS_SMEM>>>();
    knn_kernel<<<BM, 256>>>();

    // gathered per-slot MLP (16384 rows)
    mlp0g_kernel<<<NSLOT / 32, 256>>>(feats, W0, b0);

    if (fork) cudaStreamWaitEvent(0, evJ, 0);

    {
        dim3 g(512 / 128, NSLOT / 128);
        f16gemm_kernel<<<g, 128, GEMM_SMEM>>>(h1, w1i, b1, h2, NSLOT, 512, 256, GF_RELU);
    }
    {
        dim3 g(768 / 128, NSLOT / 128);
        f16gemm_kernel<<<g, 128, GEMM_SMEM>>>(h2, w2i, b2, h3, NSLOT, 768, 512, GF_RELU);
    }
    {
        // GEMM3 with fused 16-row maxpool: writes pooled [1024, 768] directly
        dim3 g(768 / 128, NSLOT / 128);
        f16gemm_kernel<<<g, 128, GEMM_SMEM>>>(h3, w3i, b3, pooled, NSLOT, 768, 768, GF_POOL);
    }

    {
        dim3 g(768 / 128, BM / 128);
        f16gemm_kernel<<<g, 128, GEMM_SMEM>>>(pooled, wn0i, bn0, t1, BM, 768, 768, GF_RELU);
        f16gemm_kernel<<<g, 128, GEMM_SMEM>>>(t1, wn1i, bn1, tok, BM, 768, 768, GF_F32OUT);
    }

    scatter_fused_kernel<<<BM, 256>>>(out, (long)out_size);
}